// round 9
// baseline (speedup 1.0000x reference)
#include <cuda_runtime.h>
#include <mma.h>
#include <cstdint>
#include <math.h>
using namespace nvcuda;

#define BATCH 64
#define C 128
#define HW 3136
#define KSPLIT 7
#define KPART 448        // HW / KSPLIT
#define NCHUNK 14        // KPART / 32
#define NUM_ITER 5
#define TRIU 8256
#define XTLD 132         // SYRK transposed-chunk ld
#define MLD 132          // NS master ld
#define NSTHR 768        // NS: 24 warps, 1 tile each (18 used per rank)

__device__ float g_G[KSPLIT][BATCH][C][C];
__device__ float g_s[KSPLIT][BATCH][C];

// SYRK: 36 tiles over 8 warps (5,5,5,5,4,4,4,4); pad guarded by (w<4||s<4)
__constant__ int8_t c_TI[8][5] = {
    {0,0,0,0,0}, {0,0,0,1,1}, {1,1,1,1,1}, {2,2,2,2,2},
    {2,3,3,3,3}, {3,3,4,4,4}, {4,4,5,5,5}, {5,6,6,7,7}};
__constant__ int8_t c_TJ[8][5] = {
    {0,1,2,3,4}, {5,6,7,1,2}, {3,4,5,6,7}, {2,3,4,5,6},
    {7,3,4,5,5}, {6,7,4,5,5}, {6,7,5,6,6}, {7,6,7,7,7}};

// NS cluster: 36 upper-tri tiles split 18/18 by rank; 1 tile per warp (w<18).
__constant__ int8_t r_TI[2][24] = {
    {0,0,0,0,0,0,0,0, 1,1,1,1,1,1,1, 2,2,2, 0,0,0,0,0,0},
    {2,2,2, 3,3,3,3,3, 4,4,4,4, 5,5,5, 6,6, 7, 0,0,0,0,0,0}};
__constant__ int8_t r_TJ[2][24] = {
    {0,1,2,3,4,5,6,7, 1,2,3,4,5,6,7, 2,3,4, 0,0,0,0,0,0},
    {5,6,7, 3,4,5,6,7, 4,5,6,7, 5,6,7, 6,7, 7, 0,0,0,0,0,0}};

__device__ __forceinline__ float rtf32(float f) {
    uint32_t u; asm("cvt.rna.tf32.f32 %0, %1;" : "=r"(u) : "f"(f));
    return __uint_as_float(u);
}
__device__ __forceinline__ uint32_t smem_u32(const void* p) {
    uint32_t a;
    asm("{ .reg .u64 t; cvta.to.shared.u64 t, %1; cvt.u32.u64 %0, t; }" : "=r"(a) : "l"(p));
    return a;
}
#define CLUSTER_SYNC() do { \
    asm volatile("barrier.cluster.arrive.aligned;" ::: "memory"); \
    asm volatile("barrier.cluster.wait.aligned;" ::: "memory"); } while (0)

typedef wmma::fragment<wmma::accumulator, 16, 16, 8, float> AccFrag;
typedef wmma::fragment<wmma::matrix_a, 16, 16, 8, wmma::precision::tf32, wmma::row_major> AFragR;
typedef wmma::fragment<wmma::matrix_a, 16, 16, 8, wmma::precision::tf32, wmma::col_major> AFragC;
typedef wmma::fragment<wmma::matrix_b, 16, 16, 8, wmma::precision::tf32, wmma::row_major> BFragR;

// ===================== Kernel 1: SYRK via wmma tf32 (unchanged) =============
__global__ __launch_bounds__(256, 2)
void syrk_tc(const float* __restrict__ x) {
    __shared__ __align__(16) float Xt[2][32 * XTLD];
    const int ks = blockIdx.x, b = blockIdx.y;
    const int t = threadIdx.x, w = t >> 5;
    const float* xb = x + (size_t)b * C * HW + (size_t)ks * KPART;

    int ti[5], tj[5];
#pragma unroll
    for (int s = 0; s < 5; s++) { ti[s] = c_TI[w][s]; tj[s] = c_TJ[w][s]; }

    AccFrag acc[5];
#pragma unroll
    for (int s = 0; s < 5; s++) wmma::fill_fragment(acc[s], 0.0f);

    const int r0 = t >> 3, seg = t & 7;
    float4 R[4];
    float rs[4] = {0.f, 0.f, 0.f, 0.f};
#pragma unroll
    for (int q = 0; q < 4; q++)
        R[q] = *(const float4*)(xb + (size_t)(r0 + q * 32) * HW + seg * 4);

    for (int c = 0; c < NCHUNK; c++) {
        float* buf = Xt[c & 1];
#pragma unroll
        for (int q = 0; q < 4; q++) {
            const float4 v = R[q];
            rs[q] += v.x + v.y + v.z + v.w;
            const int col = r0 + q * 32;
            buf[(seg * 4 + 0) * XTLD + col] = rtf32(v.x);
            buf[(seg * 4 + 1) * XTLD + col] = rtf32(v.y);
            buf[(seg * 4 + 2) * XTLD + col] = rtf32(v.z);
            buf[(seg * 4 + 3) * XTLD + col] = rtf32(v.w);
        }
        if (c + 1 < NCHUNK) {
            const float* xc = xb + (c + 1) * 32 + seg * 4;
#pragma unroll
            for (int q = 0; q < 4; q++)
                R[q] = *(const float4*)(xc + (size_t)(r0 + q * 32) * HW);
        }
        __syncthreads();
#pragma unroll
        for (int kk0 = 0; kk0 < 32; kk0 += 8) {
            const float* kbase = buf + kk0 * XTLD;
            AFragC a; BFragR bf;
#pragma unroll
            for (int s = 0; s < 5; s++) {
                if (s == 0 || ti[s] != ti[s - 1])
                    wmma::load_matrix_sync(a, kbase + ti[s] * 16, XTLD);
                if (w < 4 || s < 4) {
                    wmma::load_matrix_sync(bf, kbase + tj[s] * 16, XTLD);
                    wmma::mma_sync(acc[s], a, bf, acc[s]);
                }
            }
        }
    }

    float* Gp = &g_G[ks][b][0][0];
#pragma unroll
    for (int s = 0; s < 5; s++) {
        if (w < 4 || s < 4)
            wmma::store_matrix_sync(Gp + ti[s] * 16 * C + tj[s] * 16, acc[s], C, wmma::mem_row_major);
    }
#pragma unroll
    for (int q = 0; q < 4; q++) {
        rs[q] += __shfl_xor_sync(0xffffffffu, rs[q], 1);
        rs[q] += __shfl_xor_sync(0xffffffffu, rs[q], 2);
        rs[q] += __shfl_xor_sync(0xffffffffu, rs[q], 4);
    }
    if (seg == 0) {
#pragma unroll
        for (int q = 0; q < 4; q++) g_s[ks][b][r0 + q * 32] = rs[q];
    }
}

// ===================== Kernel 2: cluster-pair Newton-Schulz =================
#define NS_FLOATS (3 * 128 * MLD + 128 + 32)

// Copy one 16x16 block of local smem matrix (float index base mb) to peer.
__device__ __forceinline__ void cp_blk(const float* sm, uint32_t pb, int mb,
                                       int bi, int bj, int lane) {
#pragma unroll
    for (int u = 0; u < 4; u++) {
        const int idx = lane * 8 + u * 2;
        const int row = idx >> 4, col = idx & 15;
        const int off = mb + (bi * 16 + row) * MLD + bj * 16 + col;
        const uint64_t v = *(const uint64_t*)(sm + off);
        asm volatile("st.shared::cluster.b64 [%0], %1;"
                     :: "r"(pb + (uint32_t)(off * 4)), "l"(v) : "memory");
    }
}

__global__ __launch_bounds__(NSTHR, 1) __cluster_dims__(2, 1, 1)
void ns_tc(float* __restrict__ out) {
    extern __shared__ __align__(16) float sm[];
    const int YB = 0, ZB = 128 * MLD, TB = 2 * 128 * MLD;
    float* Y = sm;
    float* Z = sm + ZB;
    float* T = sm + TB;
    float* mu = sm + 3 * 128 * MLD;
    float* red = mu + 128;

    const int b = blockIdx.x >> 1;
    uint32_t rank; asm("mov.u32 %0, %%cluster_ctarank;" : "=r"(rank));
    const int t = threadIdx.x, w = t >> 5, lane = t & 31;
    const int ti = r_TI[rank][w], tj = r_TJ[rank][w];
    const bool valid = (w < 18);

    const uint32_t sb = smem_u32(sm);
    uint32_t pb;
    asm("mapa.shared::cluster.u32 %0, %1, %2;" : "=r"(pb) : "r"(sb), "r"(rank ^ 1u));

    // ---- prologue: mean, trace ----
    const float invn = 1.0f / (float)HW;
    const float* Gp[KSPLIT];
#pragma unroll
    for (int p = 0; p < KSPLIT; p++) Gp[p] = &g_G[p][b][0][0];

    if (t < 128) {
        float s = 0.f;
#pragma unroll
        for (int p = 0; p < KSPLIT; p++) s += g_s[p][b][t];
        mu[t] = s * invn;
    }
    __syncthreads();
    float dsum = 0.f;
    if (t < 128) {
        float g = 0.f;
#pragma unroll
        for (int p = 0; p < KSPLIT; p++) g += Gp[p][t * C + t];
        const float m = mu[t];
        dsum = g * invn - m * m;
    }
#pragma unroll
    for (int o = 16; o; o >>= 1) dsum += __shfl_down_sync(0xffffffffu, dsum, o);
    if (t < 128 && lane == 0) red[w] = dsum;
    __syncthreads();
    const float tr = red[0] + red[1] + red[2] + red[3];
    const float invtr = 1.0f / tr;

    // ---- Y0: each rank computes its 18 tiles (+mirror), pushes to peer ----
    CLUSTER_SYNC();   // peer smem live before remote writes
    if (valid) {
#pragma unroll
        for (int q = 0; q < 8; q++) {
            const int idx = lane * 8 + q;
            const int i = ti * 16 + (idx >> 4), j = tj * 16 + (idx & 15);
            float g = 0.f;
#pragma unroll
            for (int p = 0; p < KSPLIT; p++) g += Gp[p][i * C + j];
            const float y0 = rtf32((g * invn - mu[i] * mu[j]) * invtr);
            Y[i * MLD + j] = y0;
            Y[j * MLD + i] = y0;
        }
        cp_blk(sm, pb, YB, ti, tj, lane);
        if (tj > ti) cp_blk(sm, pb, YB, tj, ti, lane);
    }
    CLUSTER_SYNC();

    for (int it = 0; it < NUM_ITER; it++) {
        const bool lastit = (it == NUM_ITER - 1);
        const bool doZ = (it >= 1 && !lastit);

        if (it == 0) {
            // Z0 = I  =>  T0 = rna(1.5I - 0.5 Y0), Z1 = T0 (full, local)
            for (int e = t; e < C * C; e += NSTHR) {
                const int i = e >> 7, j = e & 127;
                const float v = rtf32(fmaf(-0.5f, Y[i * MLD + j], (i == j) ? 1.5f : 0.0f));
                T[i * MLD + j] = v;
                Z[i * MLD + j] = v;
            }
            __syncthreads();
        } else {
            // ---- phase 1: T = rna(-0.5 * Z@Y) (+diag 1.5), split + exchange ----
            AccFrag a1;
            wmma::fill_fragment(a1, 0.0f);
            if (valid) {
                for (int k0 = 0; k0 < C; k0 += 8) {
                    AFragR az; BFragR by;
                    wmma::load_matrix_sync(az, Z + ti * 16 * MLD + k0, MLD);
                    wmma::load_matrix_sync(by, Y + k0 * MLD + tj * 16, MLD);
                    wmma::mma_sync(a1, az, by, a1);
                }
#pragma unroll
                for (int e = 0; e < a1.num_elements; e++)
                    a1.x[e] = rtf32(-0.5f * a1.x[e]);
                wmma::store_matrix_sync(T + ti * 16 * MLD + tj * 16, a1, MLD, wmma::mem_row_major);
                if (tj > ti)
                    wmma::store_matrix_sync(T + tj * 16 * MLD + ti * 16, a1, MLD, wmma::mem_col_major);
                cp_blk(sm, pb, TB, ti, tj, lane);
                if (tj > ti) cp_blk(sm, pb, TB, tj, ti, lane);
            }
            CLUSTER_SYNC();
            if (t < 128) T[t * MLD + t] = rtf32(1.5f + T[t * MLD + t]);
            __syncthreads();
        }

        // ---- phase 2: Ynew = Y@T (+ Znew = T@Z when doZ) ----
        {
            AccFrag a2, a3;
            wmma::fill_fragment(a2, 0.0f);
            wmma::fill_fragment(a3, 0.0f);
            if (valid) {
                for (int k0 = 0; k0 < C; k0 += 8) {
                    AFragR ay, at; BFragR bt, bz;
                    wmma::load_matrix_sync(ay, Y + ti * 16 * MLD + k0, MLD);
                    wmma::load_matrix_sync(bt, T + k0 * MLD + tj * 16, MLD);
                    wmma::mma_sync(a2, ay, bt, a2);
                    if (doZ) {
                        wmma::load_matrix_sync(at, T + ti * 16 * MLD + k0, MLD);
                        wmma::load_matrix_sync(bz, Z + k0 * MLD + tj * 16, MLD);
                        wmma::mma_sync(a3, at, bz, a3);
                    }
                }
            }
            if (lastit) {
                __syncthreads();   // local reads of Y done before overwrite
                if (valid) {
                    wmma::store_matrix_sync(Y + ti * 16 * MLD + tj * 16, a2, MLD, wmma::mem_row_major);
                }
            } else {
                CLUSTER_SYNC();    // all cluster reads of Y/Z done
                if (valid) {
#pragma unroll
                    for (int e = 0; e < a2.num_elements; e++) {
                        a2.x[e] = rtf32(a2.x[e]);
                        a3.x[e] = rtf32(a3.x[e]);
                    }
                    wmma::store_matrix_sync(Y + ti * 16 * MLD + tj * 16, a2, MLD, wmma::mem_row_major);
                    if (tj > ti)
                        wmma::store_matrix_sync(Y + tj * 16 * MLD + ti * 16, a2, MLD, wmma::mem_col_major);
                    cp_blk(sm, pb, YB, ti, tj, lane);
                    if (tj > ti) cp_blk(sm, pb, YB, tj, ti, lane);
                    if (doZ) {
                        wmma::store_matrix_sync(Z + ti * 16 * MLD + tj * 16, a3, MLD, wmma::mem_row_major);
                        if (tj > ti)
                            wmma::store_matrix_sync(Z + tj * 16 * MLD + ti * 16, a3, MLD, wmma::mem_col_major);
                        cp_blk(sm, pb, ZB, ti, tj, lane);
                        if (tj > ti) cp_blk(sm, pb, ZB, tj, ti, lane);
                    }
                }
                CLUSTER_SYNC();
            }
        }
    }

    // ---- output: this rank's tiles of triu(Y * sqrt(tr)) ----
    const float s = sqrtf(tr);
    if (valid) {
        float* ob = out + (size_t)b * TRIU;
#pragma unroll
        for (int q = 0; q < 8; q++) {
            const int idx = lane * 8 + q;
            const int i = ti * 16 + (idx >> 4), j = tj * 16 + (idx & 15);
            if (j >= i)
                ob[i * (257 - i) / 2 + (j - i)] = Y[i * MLD + j] * s;
        }
    }
}

// =================== launch ==================================================
extern "C" void kernel_launch(void* const* d_in, const int* in_sizes, int n_in,
                              void* d_out, int out_size) {
    const float* x = (const float*)d_in[0];
    float* out = (float*)d_out;
    cudaFuncSetAttribute(ns_tc, cudaFuncAttributeMaxDynamicSharedMemorySize,
                         NS_FLOATS * (int)sizeof(float));
    dim3 g1(KSPLIT, BATCH);
    syrk_tc<<<g1, 256>>>(x);
    ns_tc<<<2 * BATCH, NSTHR, NS_FLOATS * sizeof(float)>>>(out);
}

// round 10
// speedup vs baseline: 1.0768x; 1.0768x over previous
#include <cuda_runtime.h>
#include <mma.h>
#include <cstdint>
#include <math.h>
using namespace nvcuda;

#define BATCH 64
#define C 128
#define HW 3136
#define KSPLIT 7
#define KPART 448        // HW / KSPLIT
#define NCHUNK 14        // KPART / 32
#define NUM_ITER 5
#define TRIU 8256
#define XTLD 132         // SYRK transposed-chunk ld
#define MLD 132          // NS master ld
#define SYTHR 384        // SYRK: 12 warps x 3 tiles = 36
#define NSTHR 576        // NS: 18 warps x 2 tiles = 36

__device__ float g_G[KSPLIT][BATCH][C][C];
__device__ float g_s[KSPLIT][BATCH][C];

// 36 upper-tri tiles over 12 warps x 3 slots (sorted by ti for A reuse)
__constant__ int8_t s_TI[12][3] = {
    {0,0,0}, {0,0,0}, {0,0,1}, {1,1,1}, {1,1,1}, {2,2,2},
    {2,2,2}, {3,3,3}, {3,3,4}, {4,4,4}, {5,5,5}, {6,6,7}};
__constant__ int8_t s_TJ[12][3] = {
    {0,1,2}, {3,4,5}, {6,7,1}, {2,3,4}, {5,6,7}, {2,3,4},
    {5,6,7}, {3,4,5}, {6,7,4}, {5,6,7}, {5,6,7}, {6,7,7}};

// 36 upper-tri tiles over 18 warps x 2 slots (sorted by ti)
__constant__ int8_t n_TI[18][2] = {
    {0,0},{0,0},{0,0},{0,0},{1,1},{1,1},{1,1},{1,2},{2,2},
    {2,2},{2,3},{3,3},{3,3},{4,4},{4,4},{5,5},{5,6},{6,7}};
__constant__ int8_t n_TJ[18][2] = {
    {0,1},{2,3},{4,5},{6,7},{1,2},{3,4},{5,6},{7,2},{3,4},
    {5,6},{7,3},{4,5},{6,7},{4,5},{6,7},{5,6},{7,6},{7,7}};

__device__ __forceinline__ float rtf32(float f) {
    uint32_t u; asm("cvt.rna.tf32.f32 %0, %1;" : "=r"(u) : "f"(f));
    return __uint_as_float(u);
}

typedef wmma::fragment<wmma::accumulator, 16, 16, 8, float> AccFrag;
typedef wmma::fragment<wmma::matrix_a, 16, 16, 8, wmma::precision::tf32, wmma::row_major> AFragR;
typedef wmma::fragment<wmma::matrix_a, 16, 16, 8, wmma::precision::tf32, wmma::col_major> AFragC;
typedef wmma::fragment<wmma::matrix_b, 16, 16, 8, wmma::precision::tf32, wmma::row_major> BFragR;

// ===================== Kernel 1: SYRK via wmma tf32 =========================
// grid (KSPLIT, BATCH), 384 threads / 12 warps x 3 tiles. Threads <256 load.
__global__ __launch_bounds__(SYTHR, 2)
void syrk_tc(const float* __restrict__ x) {
    __shared__ __align__(16) float Xt[2][32 * XTLD];
    const int ks = blockIdx.x, b = blockIdx.y;
    const int t = threadIdx.x, w = t >> 5;
    const float* xb = x + (size_t)b * C * HW + (size_t)ks * KPART;

    int ti[3], tj[3];
#pragma unroll
    for (int s = 0; s < 3; s++) { ti[s] = s_TI[w][s]; tj[s] = s_TJ[w][s]; }

    AccFrag acc[3];
#pragma unroll
    for (int s = 0; s < 3; s++) wmma::fill_fragment(acc[s], 0.0f);

    const bool ldr = (t < 256);
    const int r0 = t >> 3, seg = t & 7;     // valid when ldr
    float4 R[4];
    float rs[4] = {0.f, 0.f, 0.f, 0.f};
    if (ldr) {
#pragma unroll
        for (int q = 0; q < 4; q++)
            R[q] = *(const float4*)(xb + (size_t)(r0 + q * 32) * HW + seg * 4);
    }

    for (int c = 0; c < NCHUNK; c++) {
        float* buf = Xt[c & 1];
        if (ldr) {
#pragma unroll
            for (int q = 0; q < 4; q++) {
                const float4 v = R[q];
                rs[q] += v.x + v.y + v.z + v.w;
                const int col = r0 + q * 32;
                buf[(seg * 4 + 0) * XTLD + col] = rtf32(v.x);
                buf[(seg * 4 + 1) * XTLD + col] = rtf32(v.y);
                buf[(seg * 4 + 2) * XTLD + col] = rtf32(v.z);
                buf[(seg * 4 + 3) * XTLD + col] = rtf32(v.w);
            }
            if (c + 1 < NCHUNK) {
                const float* xc = xb + (c + 1) * 32 + seg * 4;
#pragma unroll
                for (int q = 0; q < 4; q++)
                    R[q] = *(const float4*)(xc + (size_t)(r0 + q * 32) * HW);
            }
        }
        __syncthreads();
#pragma unroll
        for (int kk0 = 0; kk0 < 32; kk0 += 8) {
            const float* kbase = buf + kk0 * XTLD;
            AFragC a; BFragR bf;
#pragma unroll
            for (int s = 0; s < 3; s++) {
                if (s == 0 || ti[s] != ti[s - 1])
                    wmma::load_matrix_sync(a, kbase + ti[s] * 16, XTLD);
                wmma::load_matrix_sync(bf, kbase + tj[s] * 16, XTLD);
                wmma::mma_sync(acc[s], a, bf, acc[s]);
            }
        }
    }

    float* Gp = &g_G[ks][b][0][0];
#pragma unroll
    for (int s = 0; s < 3; s++)
        wmma::store_matrix_sync(Gp + ti[s] * 16 * C + tj[s] * 16, acc[s], C, wmma::mem_row_major);

    if (ldr) {
#pragma unroll
        for (int q = 0; q < 4; q++) {
            rs[q] += __shfl_xor_sync(0xffffffffu, rs[q], 1);
            rs[q] += __shfl_xor_sync(0xffffffffu, rs[q], 2);
            rs[q] += __shfl_xor_sync(0xffffffffu, rs[q], 4);
        }
        if (seg == 0) {
#pragma unroll
            for (int q = 0; q < 4; q++) g_s[ks][b][r0 + q * 32] = rs[q];
        }
    }
}

// ===================== Kernel 2: fused Newton-Schulz ========================
// grid (BATCH), 576 threads / 18 warps x 2 tiles (perfect balance).
#define NS_FLOATS (3 * 128 * MLD + 128 + 32)

__global__ __launch_bounds__(NSTHR, 1)
void ns_tc(float* __restrict__ out) {
    extern __shared__ __align__(16) float sm[];
    float* Y  = sm;
    float* Z  = Y + 128 * MLD;
    float* T  = Z + 128 * MLD;
    float* mu = T + 128 * MLD;
    float* red = mu + 128;

    const int b = blockIdx.x;
    const int t = threadIdx.x, w = t >> 5, lane = t & 31;

    int ti[2], tj[2];
#pragma unroll
    for (int s = 0; s < 2; s++) { ti[s] = n_TI[w][s]; tj[s] = n_TJ[w][s]; }

    // ---- prologue: mean, trace, Y0 = rna(sigma/tr) ----
    const float invn = 1.0f / (float)HW;
    const float* Gp[KSPLIT];
#pragma unroll
    for (int p = 0; p < KSPLIT; p++) Gp[p] = &g_G[p][b][0][0];

    if (t < 128) {
        float s = 0.f;
#pragma unroll
        for (int p = 0; p < KSPLIT; p++) s += g_s[p][b][t];
        mu[t] = s * invn;
    }
    __syncthreads();
    float dsum = 0.f;
    if (t < 128) {
        float g = 0.f;
#pragma unroll
        for (int p = 0; p < KSPLIT; p++) g += Gp[p][t * C + t];
        const float m = mu[t];
        dsum = g * invn - m * m;
    }
#pragma unroll
    for (int o = 16; o; o >>= 1) dsum += __shfl_down_sync(0xffffffffu, dsum, o);
    if (t < 128 && lane == 0) red[w] = dsum;
    __syncthreads();
    const float tr = red[0] + red[1] + red[2] + red[3];
    const float invtr = 1.0f / tr;

    // Y0 from UPPER triangle of G only; mirror into smem.
    for (int pos = t; pos < TRIU; pos += NSTHR) {
        int i = (int)((257.0f - sqrtf(66049.0f - 8.0f * (float)pos)) * 0.5f);
        if (i < 0) i = 0;
        if (i > 127) i = 127;
        while (i > 0 && i * (257 - i) / 2 > pos) i--;
        while (i < 127 && (i + 1) * (257 - (i + 1)) / 2 <= pos) i++;
        const int j = i + (pos - i * (257 - i) / 2);
        float g = 0.f;
#pragma unroll
        for (int p = 0; p < KSPLIT; p++) g += Gp[p][i * C + j];
        const float y0 = rtf32((g * invn - mu[i] * mu[j]) * invtr);
        Y[i * MLD + j] = y0;
        Y[j * MLD + i] = y0;
    }
    __syncthreads();

    for (int it = 0; it < NUM_ITER; it++) {
        const bool lastit = (it == NUM_ITER - 1);
        const bool doZ = (it >= 1 && !lastit);

        if (it == 0) {
            // Z0 = I  =>  T0 = rna(1.5I - 0.5 Y0); Z1 = T0
            for (int e = t; e < C * C; e += NSTHR) {
                const int i = e >> 7, j = e & 127;
                const float v = rtf32(fmaf(-0.5f, Y[i * MLD + j], (i == j) ? 1.5f : 0.0f));
                T[i * MLD + j] = v;
                Z[i * MLD + j] = v;
            }
            __syncthreads();
        } else {
            // ---- phase 1: T = rna(-0.5 * (Z @ Y)), then diag += 1.5 ----
            AccFrag a1[2];
#pragma unroll
            for (int s = 0; s < 2; s++) wmma::fill_fragment(a1[s], 0.0f);
            for (int k0 = 0; k0 < C; k0 += 8) {
                AFragR az; BFragR by;
#pragma unroll
                for (int s = 0; s < 2; s++) {
                    if (s == 0 || ti[s] != ti[s - 1])
                        wmma::load_matrix_sync(az, Z + ti[s] * 16 * MLD + k0, MLD);
                    wmma::load_matrix_sync(by, Y + k0 * MLD + tj[s] * 16, MLD);
                    wmma::mma_sync(a1[s], az, by, a1[s]);
                }
            }
#pragma unroll
            for (int s = 0; s < 2; s++) {
#pragma unroll
                for (int e = 0; e < a1[s].num_elements; e++)
                    a1[s].x[e] = rtf32(-0.5f * a1[s].x[e]);
                wmma::store_matrix_sync(T + ti[s] * 16 * MLD + tj[s] * 16, a1[s], MLD, wmma::mem_row_major);
                if (tj[s] > ti[s])
                    wmma::store_matrix_sync(T + tj[s] * 16 * MLD + ti[s] * 16, a1[s], MLD, wmma::mem_col_major);
            }
            __syncthreads();
            if (t < 128) T[t * MLD + t] = rtf32(1.5f + T[t * MLD + t]);
            __syncthreads();
        }

        // ---- phase 2: Ynew = Y@T  (+ Znew = T@Z when doZ) ----
        {
            AccFrag a2[2], a3[2];
#pragma unroll
            for (int s = 0; s < 2; s++) { wmma::fill_fragment(a2[s], 0.0f); wmma::fill_fragment(a3[s], 0.0f); }
            for (int k0 = 0; k0 < C; k0 += 8) {
                AFragR ay, at; BFragR bt, bz;
#pragma unroll
                for (int s = 0; s < 2; s++) {
                    if (s == 0 || ti[s] != ti[s - 1]) {
                        wmma::load_matrix_sync(ay, Y + ti[s] * 16 * MLD + k0, MLD);
                        if (doZ)
                            wmma::load_matrix_sync(at, T + ti[s] * 16 * MLD + k0, MLD);
                    }
                    wmma::load_matrix_sync(bt, T + k0 * MLD + tj[s] * 16, MLD);
                    wmma::mma_sync(a2[s], ay, bt, a2[s]);
                    if (doZ) {
                        wmma::load_matrix_sync(bz, Z + k0 * MLD + tj[s] * 16, MLD);
                        wmma::mma_sync(a3[s], at, bz, a3[s]);
                    }
                }
            }
            __syncthreads();   // all reads of Y/Z complete before overwrite
            if (!lastit) {
#pragma unroll
                for (int s = 0; s < 2; s++)
#pragma unroll
                    for (int e = 0; e < a2[s].num_elements; e++) {
                        a2[s].x[e] = rtf32(a2[s].x[e]);
                        a3[s].x[e] = rtf32(a3[s].x[e]);
                    }
            }
#pragma unroll
            for (int s = 0; s < 2; s++) {
                wmma::store_matrix_sync(Y + ti[s] * 16 * MLD + tj[s] * 16, a2[s], MLD, wmma::mem_row_major);
                if (tj[s] > ti[s])
                    wmma::store_matrix_sync(Y + tj[s] * 16 * MLD + ti[s] * 16, a2[s], MLD, wmma::mem_col_major);
                if (doZ) {
                    wmma::store_matrix_sync(Z + ti[s] * 16 * MLD + tj[s] * 16, a3[s], MLD, wmma::mem_row_major);
                    if (tj[s] > ti[s])
                        wmma::store_matrix_sync(Z + tj[s] * 16 * MLD + ti[s] * 16, a3[s], MLD, wmma::mem_col_major);
                }
            }
        }
        __syncthreads();
    }

    // ---- output: triu(Y * sqrt(tr)) ----
    const float s = sqrtf(tr);
    if (t < 128) {
        const int i = t;
        float* o = out + (size_t)b * TRIU + i * (257 - i) / 2;
        const float* yr = Y + i * MLD;
        for (int j = i; j < C; j++) o[j - i] = yr[j] * s;
    }
}

// =================== launch ==================================================
extern "C" void kernel_launch(void* const* d_in, const int* in_sizes, int n_in,
                              void* d_out, int out_size) {
    const float* x = (const float*)d_in[0];
    float* out = (float*)d_out;
    cudaFuncSetAttribute(ns_tc, cudaFuncAttributeMaxDynamicSharedMemorySize,
                         NS_FLOATS * (int)sizeof(float));
    dim3 g1(KSPLIT, BATCH);
    syrk_tc<<<g1, SYTHR>>>(x);
    ns_tc<<<BATCH, NSTHR, NS_FLOATS * sizeof(float)>>>(out);
}

// round 11
// speedup vs baseline: 1.1345x; 1.0536x over previous
#include <cuda_runtime.h>
#include <mma.h>
#include <cstdint>
#include <math.h>
using namespace nvcuda;

#define BATCH 64
#define C 128
#define HW 3136
#define KSPLIT 7
#define KPART 448        // HW / KSPLIT
#define NCHUNK 14        // KPART / 32
#define NUM_ITER 5
#define TRIU 8256
#define XTLD 132         // SYRK transposed-chunk ld
#define MLD 132          // NS master ld
#define SYTHR 384        // 12 warps x 3 tiles = 36
#define NSTHR 384        // 12 warps x 3 tiles = 36

__device__ float g_G[KSPLIT][BATCH][C][C];
__device__ float g_s[KSPLIT][BATCH][C];

// 36 upper-tri tiles over 12 warps x 3 slots (sorted by ti for A reuse)
__constant__ int8_t s_TI[12][3] = {
    {0,0,0}, {0,0,0}, {0,0,1}, {1,1,1}, {1,1,1}, {2,2,2},
    {2,2,2}, {3,3,3}, {3,3,4}, {4,4,4}, {5,5,5}, {6,6,7}};
__constant__ int8_t s_TJ[12][3] = {
    {0,1,2}, {3,4,5}, {6,7,1}, {2,3,4}, {5,6,7}, {2,3,4},
    {5,6,7}, {3,4,5}, {6,7,4}, {5,6,7}, {5,6,7}, {6,7,7}};

__device__ __forceinline__ float rtf32(float f) {
    uint32_t u; asm("cvt.rna.tf32.f32 %0, %1;" : "=r"(u) : "f"(f));
    return __uint_as_float(u);
}

typedef wmma::fragment<wmma::accumulator, 16, 16, 8, float> AccFrag;
typedef wmma::fragment<wmma::matrix_a, 16, 16, 8, wmma::precision::tf32, wmma::row_major> AFragR;
typedef wmma::fragment<wmma::matrix_a, 16, 16, 8, wmma::precision::tf32, wmma::col_major> AFragC;
typedef wmma::fragment<wmma::matrix_b, 16, 16, 8, wmma::precision::tf32, wmma::row_major> BFragR;

// ===================== Kernel 1: SYRK via wmma tf32 =========================
// grid (KSPLIT, BATCH), 384 threads / 12 warps x 3 tiles. Threads <256 load.
__global__ __launch_bounds__(SYTHR, 2)
void syrk_tc(const float* __restrict__ x) {
    __shared__ __align__(16) float Xt[2][32 * XTLD];
    const int ks = blockIdx.x, b = blockIdx.y;
    const int t = threadIdx.x, w = t >> 5;
    const float* xb = x + (size_t)b * C * HW + (size_t)ks * KPART;

    int ti[3], tj[3];
#pragma unroll
    for (int s = 0; s < 3; s++) { ti[s] = s_TI[w][s]; tj[s] = s_TJ[w][s]; }

    AccFrag acc[3];
#pragma unroll
    for (int s = 0; s < 3; s++) wmma::fill_fragment(acc[s], 0.0f);

    const bool ldr = (t < 256);
    const int r0 = t >> 3, seg = t & 7;     // valid when ldr
    float4 R[4];
    float rs[4] = {0.f, 0.f, 0.f, 0.f};
    if (ldr) {
#pragma unroll
        for (int q = 0; q < 4; q++)
            R[q] = *(const float4*)(xb + (size_t)(r0 + q * 32) * HW + seg * 4);
    }

    for (int c = 0; c < NCHUNK; c++) {
        float* buf = Xt[c & 1];
        if (ldr) {
#pragma unroll
            for (int q = 0; q < 4; q++) {
                const float4 v = R[q];
                rs[q] += v.x + v.y + v.z + v.w;
                const int col = r0 + q * 32;
                buf[(seg * 4 + 0) * XTLD + col] = rtf32(v.x);
                buf[(seg * 4 + 1) * XTLD + col] = rtf32(v.y);
                buf[(seg * 4 + 2) * XTLD + col] = rtf32(v.z);
                buf[(seg * 4 + 3) * XTLD + col] = rtf32(v.w);
            }
            if (c + 1 < NCHUNK) {
                const float* xc = xb + (c + 1) * 32 + seg * 4;
#pragma unroll
                for (int q = 0; q < 4; q++)
                    R[q] = *(const float4*)(xc + (size_t)(r0 + q * 32) * HW);
            }
        }
        __syncthreads();
#pragma unroll
        for (int kk0 = 0; kk0 < 32; kk0 += 8) {
            const float* kbase = buf + kk0 * XTLD;
            AFragC a; BFragR bf;
#pragma unroll
            for (int s = 0; s < 3; s++) {
                if (s == 0 || ti[s] != ti[s - 1])
                    wmma::load_matrix_sync(a, kbase + ti[s] * 16, XTLD);
                wmma::load_matrix_sync(bf, kbase + tj[s] * 16, XTLD);
                wmma::mma_sync(acc[s], a, bf, acc[s]);
            }
        }
    }

    float* Gp = &g_G[ks][b][0][0];
#pragma unroll
    for (int s = 0; s < 3; s++)
        wmma::store_matrix_sync(Gp + ti[s] * 16 * C + tj[s] * 16, acc[s], C, wmma::mem_row_major);

    if (ldr) {
#pragma unroll
        for (int q = 0; q < 4; q++) {
            rs[q] += __shfl_xor_sync(0xffffffffu, rs[q], 1);
            rs[q] += __shfl_xor_sync(0xffffffffu, rs[q], 2);
            rs[q] += __shfl_xor_sync(0xffffffffu, rs[q], 4);
        }
        if (seg == 0) {
#pragma unroll
            for (int q = 0; q < 4; q++) g_s[ks][b][r0 + q * 32] = rs[q];
        }
    }
}

// ===================== Kernel 2: fused Newton-Schulz ========================
// grid (BATCH), 384 threads / 12 warps x 3 tiles; shared-B phase 2:
// Znext = sym(Z@T) == sym of transpose of T@Z (exact for symmetric Z,T).
#define NS_FLOATS (3 * 128 * MLD + 128 + 16)

__global__ __launch_bounds__(NSTHR, 1)
void ns_tc(float* __restrict__ out) {
    extern __shared__ __align__(16) float sm[];
    float* Y  = sm;
    float* Z  = Y + 128 * MLD;
    float* T  = Z + 128 * MLD;
    float* mu = T + 128 * MLD;
    float* red = mu + 128;

    const int b = blockIdx.x;
    const int t = threadIdx.x, w = t >> 5, lane = t & 31;

    int ti[3], tj[3];
#pragma unroll
    for (int s = 0; s < 3; s++) { ti[s] = s_TI[w][s]; tj[s] = s_TJ[w][s]; }

    // ---- prologue: mean, trace, Y0 = rna(sigma/tr) ----
    const float invn = 1.0f / (float)HW;
    const float* Gp[KSPLIT];
#pragma unroll
    for (int p = 0; p < KSPLIT; p++) Gp[p] = &g_G[p][b][0][0];

    if (t < 128) {
        float s = 0.f;
#pragma unroll
        for (int p = 0; p < KSPLIT; p++) s += g_s[p][b][t];
        mu[t] = s * invn;
    }
    __syncthreads();
    float dsum = 0.f;
    if (t < 128) {
        float g = 0.f;
#pragma unroll
        for (int p = 0; p < KSPLIT; p++) g += Gp[p][t * C + t];
        const float m = mu[t];
        dsum = g * invn - m * m;
    }
#pragma unroll
    for (int o = 16; o; o >>= 1) dsum += __shfl_down_sync(0xffffffffu, dsum, o);
    if (t < 128 && lane == 0) red[w] = dsum;
    __syncthreads();
    const float tr = red[0] + red[1] + red[2] + red[3];
    const float invtr = 1.0f / tr;

    // Y0 from UPPER triangle of G only; mirror into smem.
    for (int pos = t; pos < TRIU; pos += NSTHR) {
        int i = (int)((257.0f - sqrtf(66049.0f - 8.0f * (float)pos)) * 0.5f);
        if (i < 0) i = 0;
        if (i > 127) i = 127;
        while (i > 0 && i * (257 - i) / 2 > pos) i--;
        while (i < 127 && (i + 1) * (257 - (i + 1)) / 2 <= pos) i++;
        const int j = i + (pos - i * (257 - i) / 2);
        float g = 0.f;
#pragma unroll
        for (int p = 0; p < KSPLIT; p++) g += Gp[p][i * C + j];
        const float y0 = rtf32((g * invn - mu[i] * mu[j]) * invtr);
        Y[i * MLD + j] = y0;
        Y[j * MLD + i] = y0;
    }
    __syncthreads();

    for (int it = 0; it < NUM_ITER; it++) {
        const bool lastit = (it == NUM_ITER - 1);
        const bool doZ = (it >= 1 && !lastit);

        if (it == 0) {
            // Z0 = I  =>  T0 = rna(1.5I - 0.5 Y0); Z1 = T0
            for (int e = t; e < C * C; e += NSTHR) {
                const int i = e >> 7, j = e & 127;
                const float v = rtf32(fmaf(-0.5f, Y[i * MLD + j], (i == j) ? 1.5f : 0.0f));
                T[i * MLD + j] = v;
                Z[i * MLD + j] = v;
            }
            __syncthreads();
        } else {
            // ---- phase 1: T = rna(-0.5 * (Z @ Y)), then diag += 1.5 ----
            AccFrag a1[3];
#pragma unroll
            for (int s = 0; s < 3; s++) wmma::fill_fragment(a1[s], 0.0f);
            for (int k0 = 0; k0 < C; k0 += 8) {
                AFragR az; BFragR by;
#pragma unroll
                for (int s = 0; s < 3; s++) {
                    if (s == 0 || ti[s] != ti[s - 1])
                        wmma::load_matrix_sync(az, Z + ti[s] * 16 * MLD + k0, MLD);
                    wmma::load_matrix_sync(by, Y + k0 * MLD + tj[s] * 16, MLD);
                    wmma::mma_sync(a1[s], az, by, a1[s]);
                }
            }
#pragma unroll
            for (int s = 0; s < 3; s++) {
#pragma unroll
                for (int e = 0; e < a1[s].num_elements; e++)
                    a1[s].x[e] = rtf32(-0.5f * a1[s].x[e]);
                wmma::store_matrix_sync(T + ti[s] * 16 * MLD + tj[s] * 16, a1[s], MLD, wmma::mem_row_major);
                if (tj[s] > ti[s])
                    wmma::store_matrix_sync(T + tj[s] * 16 * MLD + ti[s] * 16, a1[s], MLD, wmma::mem_col_major);
            }
            __syncthreads();
            if (t < 128) T[t * MLD + t] = rtf32(1.5f + T[t * MLD + t]);
            __syncthreads();
        }

        // ---- phase 2: Ynew = Y@T ; Znew = sym(Z@T) -- shared B fragment ----
        {
            AccFrag a2[3], a3[3];
#pragma unroll
            for (int s = 0; s < 3; s++) { wmma::fill_fragment(a2[s], 0.0f); wmma::fill_fragment(a3[s], 0.0f); }
            for (int k0 = 0; k0 < C; k0 += 8) {
                AFragR ay, az; BFragR bt;
#pragma unroll
                for (int s = 0; s < 3; s++) {
                    if (s == 0 || ti[s] != ti[s - 1]) {
                        wmma::load_matrix_sync(ay, Y + ti[s] * 16 * MLD + k0, MLD);
                        if (doZ)
                            wmma::load_matrix_sync(az, Z + ti[s] * 16 * MLD + k0, MLD);
                    }
                    wmma::load_matrix_sync(bt, T + k0 * MLD + tj[s] * 16, MLD);
                    wmma::mma_sync(a2[s], ay, bt, a2[s]);
                    if (doZ)
                        wmma::mma_sync(a3[s], az, bt, a3[s]);
                }
            }
            __syncthreads();   // all reads of Y/Z complete before overwrite
            if (!lastit) {
#pragma unroll
                for (int s = 0; s < 3; s++)
#pragma unroll
                    for (int e = 0; e < a2[s].num_elements; e++) {
                        a2[s].x[e] = rtf32(a2[s].x[e]);
                        a3[s].x[e] = rtf32(a3[s].x[e]);
                    }
            }
#pragma unroll
            for (int s = 0; s < 3; s++) {
                wmma::store_matrix_sync(Y + ti[s] * 16 * MLD + tj[s] * 16, a2[s], MLD, wmma::mem_row_major);
                if (tj[s] > ti[s])
                    wmma::store_matrix_sync(Y + tj[s] * 16 * MLD + ti[s] * 16, a2[s], MLD, wmma::mem_col_major);
                if (doZ) {
                    wmma::store_matrix_sync(Z + ti[s] * 16 * MLD + tj[s] * 16, a3[s], MLD, wmma::mem_row_major);
                    if (tj[s] > ti[s])
                        wmma::store_matrix_sync(Z + tj[s] * 16 * MLD + ti[s] * 16, a3[s], MLD, wmma::mem_col_major);
                }
            }
        }
        __syncthreads();
    }

    // ---- output: triu(Y * sqrt(tr)) ----
    const float s = sqrtf(tr);
    if (t < 128) {
        const int i = t;
        float* o = out + (size_t)b * TRIU + i * (257 - i) / 2;
        const float* yr = Y + i * MLD;
        for (int j = i; j < C; j++) o[j - i] = yr[j] * s;
    }
}

// =================== launch ==================================================
extern "C" void kernel_launch(void* const* d_in, const int* in_sizes, int n_in,
                              void* d_out, int out_size) {
    const float* x = (const float*)d_in[0];
    float* out = (float*)d_out;
    cudaFuncSetAttribute(ns_tc, cudaFuncAttributeMaxDynamicSharedMemorySize,
                         NS_FLOATS * (int)sizeof(float));
    dim3 g1(KSPLIT, BATCH);
    syrk_tc<<<g1, SYTHR>>>(x);
    ns_tc<<<BATCH, NSTHR, NS_FLOATS * sizeof(float)>>>(out);
}